// round 2
// baseline (speedup 1.0000x reference)
#include <cuda_runtime.h>
#include <math.h>
#include <stdint.h>

// ---------------------------------------------------------------------------
// ChildSumTreeLSTM on a perfect binary tree, N = 131071 = 2^17 - 1.
//
// Decomposition:
//   Y[N,1024]  = X @ [W_ioux; W_fx]^T + [b_ioux+b_iouh ; b_fx+b_fh]   (once)
//   leaves:      c = sig(i)*tanh(u), h = sig(o)*tanh(c)   from Y rows
//   per level (bottom-up):
//     G[2c,1024] = h_children @ [W_iouh; W_fh]^T          (children rows are
//                                                          contiguous in h)
//     combine:  iou = Y[n,0:768] + G[l,0:768] + G[r,0:768]
//               f_k = sigmoid(G[k,768:1024] + Y[n,768:1024])
//               c_n = sig(i)*tanh(u) + f_l*c_l + f_r*c_r
//               h_n = sig(o)*tanh(c_n)
// All fp32.
// ---------------------------------------------------------------------------

#define NN 131071

// scratch (device globals; no allocations allowed)
static __device__ float g_Y[(size_t)131072 * 1024];  // packed [ioub | fxb]
static __device__ float g_G[(size_t)65536 * 1024];   // per-level child GEMM out
static __device__ float g_h[(size_t)131072 * 256];
static __device__ float g_c[(size_t)131072 * 256];
static __device__ float g_W1[1024 * 256];            // [W_ioux; W_fx]
static __device__ float g_W2[1024 * 256];            // [W_iouh; W_fh]
static __device__ float g_b1[1024];                  // folded biases

__device__ __forceinline__ float sigmoidf_(float x) {
    return 1.0f / (1.0f + expf(-x));
}

// ---------------------------------------------------------------------------
__global__ void pack_weights_kernel(const float* __restrict__ W_ioux,
                                    const float* __restrict__ b_ioux,
                                    const float* __restrict__ W_iouh,
                                    const float* __restrict__ b_iouh,
                                    const float* __restrict__ W_fx,
                                    const float* __restrict__ b_fx,
                                    const float* __restrict__ W_fh,
                                    const float* __restrict__ b_fh) {
    int i = blockIdx.x * blockDim.x + threadIdx.x;
    if (i >= 1024 * 256) return;
    int r = i >> 8;
    int c = i & 255;
    g_W1[i] = (r < 768) ? W_ioux[i] : W_fx[(r - 768) * 256 + c];
    g_W2[i] = (r < 768) ? W_iouh[i] : W_fh[(r - 768) * 256 + c];
    if (c == 0)
        g_b1[r] = (r < 768) ? (b_ioux[r] + b_iouh[r])
                            : (b_fx[r - 768] + b_fh[r - 768]);
}

// ---------------------------------------------------------------------------
// C[M,1024] = A[M,256] @ B[1024,256]^T (+ bias)
// 64x64 block tile, K-chunk 16, 256 threads, 4x4 register microtile.
__device__ __forceinline__ void gemm_body(const float* __restrict__ A,
                                          const float* __restrict__ B,
                                          const float* __restrict__ bias,
                                          float* __restrict__ C, int M) {
    __shared__ float As[16][68];  // [k][m], stride 68 keeps float4 alignment
    __shared__ float Bs[16][68];  // [k][n]

    const int bm = blockIdx.x * 64;
    const int bn = blockIdx.y * 64;
    const int tid = (int)threadIdx.x;
    const int tx = tid & 15;
    const int ty = tid >> 4;
    const int lr = tid >> 2;        // 0..63: tile row loaded by this thread
    const int lk = (tid & 3) << 2;  // 0,4,8,12: k offset

    float acc[4][4];
#pragma unroll
    for (int i = 0; i < 4; i++)
#pragma unroll
        for (int j = 0; j < 4; j++) acc[i][j] = 0.0f;

    for (int k0 = 0; k0 < 256; k0 += 16) {
        float4 av = make_float4(0.f, 0.f, 0.f, 0.f);
        const int am = bm + lr;
        if (am < M)
            av = *reinterpret_cast<const float4*>(A + (size_t)am * 256 + k0 + lk);
        As[lk + 0][lr] = av.x;
        As[lk + 1][lr] = av.y;
        As[lk + 2][lr] = av.z;
        As[lk + 3][lr] = av.w;

        const float4 bv =
            *reinterpret_cast<const float4*>(B + (size_t)(bn + lr) * 256 + k0 + lk);
        Bs[lk + 0][lr] = bv.x;
        Bs[lk + 1][lr] = bv.y;
        Bs[lk + 2][lr] = bv.z;
        Bs[lk + 3][lr] = bv.w;

        __syncthreads();

#pragma unroll
        for (int k = 0; k < 16; k++) {
            const float4 a = *reinterpret_cast<const float4*>(&As[k][ty << 2]);
            const float4 b = *reinterpret_cast<const float4*>(&Bs[k][tx << 2]);
            acc[0][0] += a.x * b.x; acc[0][1] += a.x * b.y;
            acc[0][2] += a.x * b.z; acc[0][3] += a.x * b.w;
            acc[1][0] += a.y * b.x; acc[1][1] += a.y * b.y;
            acc[1][2] += a.y * b.z; acc[1][3] += a.y * b.w;
            acc[2][0] += a.z * b.x; acc[2][1] += a.z * b.y;
            acc[2][2] += a.z * b.z; acc[2][3] += a.z * b.w;
            acc[3][0] += a.w * b.x; acc[3][1] += a.w * b.y;
            acc[3][2] += a.w * b.z; acc[3][3] += a.w * b.w;
        }
        __syncthreads();
    }

#pragma unroll
    for (int i = 0; i < 4; i++) {
        const int row = bm + (ty << 2) + i;
        if (row >= M) continue;
#pragma unroll
        for (int j = 0; j < 4; j++) {
            const int col = bn + (tx << 2) + j;
            float v = acc[i][j];
            if (bias) v += bias[col];
            C[(size_t)row * 1024 + col] = v;
        }
    }
}

__global__ void gemm_init_kernel(const float* __restrict__ X, int M) {
    gemm_body(X, g_W1, g_b1, g_Y, M);
}

__global__ void gemm_rec_kernel(int cs, int rows) {
    gemm_body(g_h + (size_t)cs * 256, g_W2, nullptr, g_G, rows);
}

// ---------------------------------------------------------------------------
__global__ void leaf_kernel(int start) {
    const int n = start + blockIdx.x;
    const int d = (int)threadIdx.x;
    const float* Yn = g_Y + (size_t)n * 1024;
    const float cv = sigmoidf_(Yn[d]) * tanhf(Yn[512 + d]);
    const float hv = sigmoidf_(Yn[256 + d]) * tanhf(cv);
    g_c[(size_t)n * 256 + d] = cv;
    g_h[(size_t)n * 256 + d] = hv;
}

__global__ void combine_kernel(int start, int cs) {
    const int j = (int)blockIdx.x;   // node index within level
    const int d = (int)threadIdx.x;  // 0..255
    const int n = start + j;
    const float* Yn = g_Y + (size_t)n * 1024;
    const float* Gl = g_G + (size_t)(2 * j) * 1024;
    const float* Gr = g_G + (size_t)(2 * j + 1) * 1024;

    const float iv = Yn[d] + Gl[d] + Gr[d];
    const float ov = Yn[256 + d] + Gl[256 + d] + Gr[256 + d];
    const float uv = Yn[512 + d] + Gl[512 + d] + Gr[512 + d];
    const float fxv = Yn[768 + d];
    const float fl = sigmoidf_(Gl[768 + d] + fxv);
    const float fr = sigmoidf_(Gr[768 + d] + fxv);
    const float cl = g_c[(size_t)(cs + 2 * j) * 256 + d];
    const float cr = g_c[(size_t)(cs + 2 * j + 1) * 256 + d];

    const float cv = sigmoidf_(iv) * tanhf(uv) + fl * cl + fr * cr;
    const float hv = sigmoidf_(ov) * tanhf(cv);
    g_c[(size_t)n * 256 + d] = cv;
    g_h[(size_t)n * 256 + d] = hv;
}

__global__ void write_out_kernel(float* __restrict__ out) {
    const int d = (int)threadIdx.x;  // 0..255
    out[d] = g_c[d];                 // c[0]
    out[256 + d] = g_h[d];           // h[0]
}

// ---------------------------------------------------------------------------
extern "C" void kernel_launch(void* const* d_in, const int* in_sizes, int n_in,
                              void* d_out, int out_size) {
    const float* X      = (const float*)d_in[0];
    const float* W_ioux = (const float*)d_in[1];
    const float* b_ioux = (const float*)d_in[2];
    const float* W_iouh = (const float*)d_in[3];
    const float* b_iouh = (const float*)d_in[4];
    const float* W_fx   = (const float*)d_in[5];
    const float* b_fx   = (const float*)d_in[6];
    const float* W_fh   = (const float*)d_in[7];
    const float* b_fh   = (const float*)d_in[8];
    float* out = (float*)d_out;

    // pack weights + folded biases
    pack_weights_kernel<<<(1024 * 256 + 255) / 256, 256>>>(
        W_ioux, b_ioux, W_iouh, b_iouh, W_fx, b_fx, W_fh, b_fh);

    // Y = X @ W1^T + b1   (M = 131071, N = 1024, K = 256)
    gemm_init_kernel<<<dim3((NN + 63) / 64, 16), 256>>>(X, NN);

    // leaves: level 16, start 65535, count 65536
    leaf_kernel<<<65536, 256>>>(65535);

    // internal levels bottom-up
    for (int lvl = 15; lvl >= 0; lvl--) {
        const int count = 1 << lvl;
        const int start = count - 1;
        const int cs = 2 * start + 1;
        const int rows = 2 * count;
        gemm_rec_kernel<<<dim3((rows + 63) / 64, 16), 256>>>(cs, rows);
        combine_kernel<<<count, 256>>>(start, cs);
    }

    write_out_kernel<<<1, 256>>>(out);
}